// round 3
// baseline (speedup 1.0000x reference)
#include <cuda_runtime.h>

// Net_12403865551680 — 2-layer GCN + mean-pool + Kronecker BN-MLP head.
// R1: project-then-aggregate + f32x2 GEMM + atomic scatter  (596 us)
// R2: CSR + gather (629 us — CSR build cost not recovered)
// R3: thread-per-(node,chunk) gathers with x2 unroll, proj1 moved to launch
//     slot 4 so ncu profiles it, pooldiv fused into mlp1.

typedef unsigned long long ull;

#define NN 100000
#define NE 1600000
#define NG 1024

// ---------------- scratch (static device allocations) ----------------
__device__ __align__(128) float d_hp1[NN * 100];   // feat@W1 (pre-aggregation)
__device__ __align__(128) float d_h1[NN * 100];    // relu(agg(hp1)/deg + b1)
__device__ __align__(128) float d_hp2[NN * 20];    // h1@W2
__device__ int   d_deg[NN];
__device__ int   d_rowstart[NN + 1];
__device__ int   d_cursor[NN];
__device__ int   d_csr[NE];         // src ids grouped by dst
__device__ __align__(128) float d_gsum[NG * 20];
__device__ float d_gcnt[NG];
__device__ __align__(128) float d_y1[NG * 128];
__device__ __align__(128) float d_y2[NG * 32];
__device__ float d_stat1[2 * 128];  // mean | rstd
__device__ float d_stat2[2 * 32];

// ---------------- packed f32x2 helpers ----------------
__device__ __forceinline__ ull dup2(float x) {
    ull r; asm("mov.b64 %0, {%1, %1};" : "=l"(r) : "f"(x)); return r;
}
__device__ __forceinline__ void fma2(ull& d, ull a, ull b) {
    asm("fma.rn.f32x2 %0, %1, %2, %0;" : "+l"(d) : "l"(a), "l"(b));
}
__device__ __forceinline__ float f2lo(ull v) { return __uint_as_float((unsigned)v); }
__device__ __forceinline__ float f2hi(ull v) { return __uint_as_float((unsigned)(v >> 32)); }

// ---------------- zero the (small) accumulators ----------------
__global__ void zero_kernel() {
    int i = blockIdx.x * blockDim.x + threadIdx.x;
    int st = gridDim.x * blockDim.x;
    for (int j = i; j < NN; j += st) d_deg[j] = 0;
    for (int j = i; j < NG * 20; j += st) d_gsum[j] = 0.f;
    for (int j = i; j < NG; j += st) d_gcnt[j] = 0.f;
}

// ---------------- degree histogram ----------------
__global__ void deg_kernel(const int* __restrict__ dst) {
    int i = blockIdx.x * blockDim.x + threadIdx.x;
    if (i < NE) atomicAdd(&d_deg[dst[i]], 1);
}

// ---------------- single-block exclusive scan of deg -> rowstart, cursor ----------------
__global__ void __launch_bounds__(1024) scan_kernel() {
    constexpr int T = 1024;
    constexpr int ITEMS = (NN + T - 1) / T;   // 98
    int t = threadIdx.x;
    int base = t * ITEMS;
    int sum = 0;
    for (int i = 0; i < ITEMS; i++) {
        int idx = base + i;
        if (idx < NN) sum += d_deg[idx];
    }
    __shared__ int wsum[32];
    int lane = t & 31, w = t >> 5;
    int v = sum;
#pragma unroll
    for (int o = 1; o < 32; o <<= 1) {
        int u = __shfl_up_sync(0xffffffffu, v, o);
        if (lane >= o) v += u;
    }
    if (lane == 31) wsum[w] = v;
    __syncthreads();
    if (w == 0) {
        int x = wsum[lane];
#pragma unroll
        for (int o = 1; o < 32; o <<= 1) {
            int u = __shfl_up_sync(0xffffffffu, x, o);
            if (lane >= o) x += u;
        }
        wsum[lane] = x;
    }
    __syncthreads();
    int excl = v - sum + (w > 0 ? wsum[w - 1] : 0);
    int run = excl;
    for (int i = 0; i < ITEMS; i++) {
        int idx = base + i;
        if (idx < NN) {
            d_rowstart[idx] = run;
            d_cursor[idx] = run;
            run += d_deg[idx];
        }
    }
    if (t == T - 1) d_rowstart[NN] = NE;
}

// ---------------- CSR fill: group src ids by dst ----------------
__global__ void fill_kernel(const int* __restrict__ src, const int* __restrict__ dst) {
    int e = blockIdx.x * blockDim.x + threadIdx.x;
    if (e >= NE) return;
    int d = dst[e];
    int p = atomicAdd(&d_cursor[d], 1);
    d_csr[p] = src[e];
}

// ---------------- tiled GEMM: Y[M,N] = X[M,K] @ W[K,N], f32x2 packed ----------------
template<int N, int OT, int NT, int NPT, int KC, int LAYER>
__global__ void __launch_bounds__(OT * NT) proj_kernel(const float* __restrict__ Xin,
                                                       const float* __restrict__ W,
                                                       int M, int K)
{
    const float* __restrict__ X = (LAYER == 1) ? Xin : (const float*)d_h1;
    float* __restrict__ Y = (LAYER == 1) ? d_hp1 : d_hp2;

    constexpr int NODE_TILE = NT * NPT;
    constexpr int XSS = NODE_TILE + 2;
    constexpr int NTH = OT * NT;
    __shared__ float Xs[KC * XSS];
    __shared__ float Ws[KC * N];

    const int tid = threadIdx.x;
    const int ot = tid % OT;
    const int nt = tid / OT;
    const int nodeBase = blockIdx.x * NODE_TILE;

    ull acc[NPT / 2][4];
#pragma unroll
    for (int i = 0; i < NPT / 2; i++) { acc[i][0] = 0; acc[i][1] = 0; acc[i][2] = 0; acc[i][3] = 0; }

    for (int kc0 = 0; kc0 < K; kc0 += KC) {
        __syncthreads();
        for (int idx = tid; idx < KC * NODE_TILE; idx += NTH) {
            int k = idx % KC;
            int n = idx / KC;
            int gn = nodeBase + n;
            float v = (gn < M) ? X[gn * K + kc0 + k] : 0.f;
            Xs[k * XSS + n] = v;
        }
        for (int idx = tid; idx < KC * N; idx += NTH) {
            int o = idx % N;
            int k = idx / N;
            Ws[idx] = W[(kc0 + k) * N + o];
        }
        __syncthreads();
#pragma unroll 4
        for (int k = 0; k < KC; k++) {
            float4 wv = *(const float4*)&Ws[k * N + ot * 4];
            ull w0 = dup2(wv.x), w1 = dup2(wv.y), w2 = dup2(wv.z), w3 = dup2(wv.w);
#pragma unroll
            for (int i = 0; i < NPT / 2; i++) {
                ull a = *(const ull*)&Xs[k * XSS + nt * NPT + 2 * i];
                fma2(acc[i][0], a, w0);
                fma2(acc[i][1], a, w1);
                fma2(acc[i][2], a, w2);
                fma2(acc[i][3], a, w3);
            }
        }
    }
#pragma unroll
    for (int i = 0; i < NPT / 2; i++) {
        int n0 = nodeBase + nt * NPT + 2 * i;
        float4 r0 = make_float4(f2lo(acc[i][0]), f2lo(acc[i][1]), f2lo(acc[i][2]), f2lo(acc[i][3]));
        float4 r1 = make_float4(f2hi(acc[i][0]), f2hi(acc[i][1]), f2hi(acc[i][2]), f2hi(acc[i][3]));
        if (n0 < M)     *(float4*)&Y[n0 * N + ot * 4] = r0;
        if (n0 + 1 < M) *(float4*)&Y[(n0 + 1) * N + ot * 4] = r1;
    }
}

// ---------------- layer-1 aggregation: thread-per-(node,chunk) gather ----------------
// h1[n] = relu( (deg>0 ? mean_{s in csr[n]} hp1[s] : hp1[n]) + b1 ), 25 chunks of 4
__global__ void __launch_bounds__(256) gather1_kernel(const float* __restrict__ b1) {
    int i = blockIdx.x * 256 + threadIdx.x;
    if (i >= NN * 25) return;
    int n = i / 25;
    int c = i - n * 25;
    int row0 = d_rowstart[n];
    int row1 = d_rowstart[n + 1];
    int deg = row1 - row0;

    float4 a0 = make_float4(0.f, 0.f, 0.f, 0.f);
    float4 a1 = make_float4(0.f, 0.f, 0.f, 0.f);
    int j = row0;
    for (; j + 1 < row1; j += 2) {
        int s0 = __ldg(&d_csr[j]);
        int s1 = __ldg(&d_csr[j + 1]);
        float4 f0 = *(const float4*)(d_hp1 + s0 * 100 + c * 4);
        float4 f1 = *(const float4*)(d_hp1 + s1 * 100 + c * 4);
        a0.x += f0.x; a0.y += f0.y; a0.z += f0.z; a0.w += f0.w;
        a1.x += f1.x; a1.y += f1.y; a1.z += f1.z; a1.w += f1.w;
    }
    if (j < row1) {
        int s = __ldg(&d_csr[j]);
        float4 f = *(const float4*)(d_hp1 + s * 100 + c * 4);
        a0.x += f.x; a0.y += f.y; a0.z += f.z; a0.w += f.w;
    }
    float4 v;
    if (deg > 0) {
        float inv = 1.f / (float)deg;
        v = make_float4((a0.x + a1.x) * inv, (a0.y + a1.y) * inv,
                        (a0.z + a1.z) * inv, (a0.w + a1.w) * inv);
    } else {
        v = *(const float4*)(d_hp1 + n * 100 + c * 4);
    }
    float4 b = *(const float4*)(b1 + c * 4);
    float4 r = make_float4(fmaxf(v.x + b.x, 0.f), fmaxf(v.y + b.y, 0.f),
                           fmaxf(v.z + b.z, 0.f), fmaxf(v.w + b.w, 0.f));
    *(float4*)(d_h1 + n * 100 + c * 4) = r;
}

// ---------------- layer-2 aggregation + fused graph pooling ----------------
__global__ void __launch_bounds__(256) gather2_kernel(const float* __restrict__ b2,
                                                      const int* __restrict__ n2g) {
    int i = blockIdx.x * 256 + threadIdx.x;
    if (i >= NN * 5) return;
    int n = i / 5;
    int c = i - n * 5;
    int row0 = d_rowstart[n];
    int row1 = d_rowstart[n + 1];
    int deg = row1 - row0;

    float4 a0 = make_float4(0.f, 0.f, 0.f, 0.f);
    float4 a1 = make_float4(0.f, 0.f, 0.f, 0.f);
    int j = row0;
    for (; j + 1 < row1; j += 2) {
        int s0 = __ldg(&d_csr[j]);
        int s1 = __ldg(&d_csr[j + 1]);
        float4 f0 = *(const float4*)(d_hp2 + s0 * 20 + c * 4);
        float4 f1 = *(const float4*)(d_hp2 + s1 * 20 + c * 4);
        a0.x += f0.x; a0.y += f0.y; a0.z += f0.z; a0.w += f0.w;
        a1.x += f1.x; a1.y += f1.y; a1.z += f1.z; a1.w += f1.w;
    }
    if (j < row1) {
        int s = __ldg(&d_csr[j]);
        float4 f = *(const float4*)(d_hp2 + s * 20 + c * 4);
        a0.x += f.x; a0.y += f.y; a0.z += f.z; a0.w += f.w;
    }
    float4 v;
    if (deg > 0) {
        float inv = 1.f / (float)deg;
        v = make_float4((a0.x + a1.x) * inv, (a0.y + a1.y) * inv,
                        (a0.z + a1.z) * inv, (a0.w + a1.w) * inv);
    } else {
        v = *(const float4*)(d_hp2 + n * 20 + c * 4);
    }
    float4 b = *(const float4*)(b2 + c * 4);
    float4 r = make_float4(fmaxf(v.x + b.x, 0.f), fmaxf(v.y + b.y, 0.f),
                           fmaxf(v.z + b.z, 0.f), fmaxf(v.w + b.w, 0.f));
    int g = n2g[n];
    float* gs = d_gsum + g * 20 + c * 4;
    atomicAdd(gs + 0, r.x);
    atomicAdd(gs + 1, r.y);
    atomicAdd(gs + 2, r.z);
    atomicAdd(gs + 3, r.w);
    if (c == 0) atomicAdd(&d_gcnt[g], 1.f);
}

// ---------------- Kronecker-fused GEMM: y1 = (hg (x) sf) @ Wf1 + bf1 ----------------
// pooldiv fused: hg = gsum / max(gcnt,1)
__global__ void __launch_bounds__(128) mlp1_kernel(const float* __restrict__ sf,
                                                   const float* __restrict__ Wf1,
                                                   const float* __restrict__ bf1) {
    __shared__ float fs[16 * 640];
    __shared__ float inv[16];
    int g0 = blockIdx.x * 16;
    int tid = threadIdx.x;
    if (tid < 16) inv[tid] = 1.f / fmaxf(d_gcnt[g0 + tid], 1.f);
    __syncthreads();
    for (int idx = tid; idx < 16 * 640; idx += 128) {
        int g = idx / 640;
        int j = idx - g * 640;
        int k = j >> 5, s = j & 31;
        fs[idx] = d_gsum[(g0 + g) * 20 + k] * inv[g] * sf[(g0 + g) * 32 + s];
    }
    __syncthreads();
    int o = tid;
    float acc[16];
#pragma unroll
    for (int g = 0; g < 16; g++) acc[g] = 0.f;
    for (int j = 0; j < 640; j++) {
        float w = Wf1[j * 128 + o];
#pragma unroll
        for (int g = 0; g < 16; g++) acc[g] += fs[g * 640 + j] * w;
    }
    float b = bf1[o];
#pragma unroll
    for (int g = 0; g < 16; g++) d_y1[(g0 + g) * 128 + o] = acc[g] + b;
}

// ---------------- BatchNorm stats (biased, training mode) ----------------
template<int C>
__global__ void bnstats_kernel() {
    const float* __restrict__ Y = (C == 128) ? (const float*)d_y1 : (const float*)d_y2;
    float* __restrict__ stat = (C == 128) ? d_stat1 : d_stat2;
    int c = blockIdx.x;
    float s = 0.f, q = 0.f;
    for (int r = threadIdx.x; r < NG; r += 256) {
        float x = Y[r * C + c];
        s += x; q += x * x;
    }
#pragma unroll
    for (int o = 16; o > 0; o >>= 1) {
        s += __shfl_down_sync(0xffffffff, s, o);
        q += __shfl_down_sync(0xffffffff, q, o);
    }
    __shared__ float ss[8], sq[8];
    int w = threadIdx.x >> 5, l = threadIdx.x & 31;
    if (l == 0) { ss[w] = s; sq[w] = q; }
    __syncthreads();
    if (threadIdx.x == 0) {
        float S = 0.f, Q = 0.f;
#pragma unroll
        for (int i = 0; i < 8; i++) { S += ss[i]; Q += sq[i]; }
        float mu = S / (float)NG;
        float var = Q / (float)NG - mu * mu;
        stat[c] = mu;
        stat[C + c] = rsqrtf(var + 1e-5f);
    }
}

// ---------------- y2 = bn_relu(y1) @ Wf2 + bf2 ----------------
__global__ void mlp2_kernel(const float* __restrict__ Wf2, const float* __restrict__ bf2,
                            const float* __restrict__ g1, const float* __restrict__ be1) {
    int i = blockIdx.x * blockDim.x + threadIdx.x;  // 1024*32
    int g = i >> 5, o = i & 31;
    float acc = 0.f;
    for (int k = 0; k < 128; k++) {
        float x = d_y1[g * 128 + k];
        x = fmaxf((x - d_stat1[k]) * d_stat1[128 + k] * g1[k] + be1[k], 0.f);
        acc += x * Wf2[k * 32 + o];
    }
    d_y2[g * 32 + o] = acc + bf2[o];
}

// ---------------- out = bn_relu(y2) @ Wf3 + bf3 ----------------
__global__ void mlp3_kernel(const float* __restrict__ Wf3, const float* __restrict__ bf3,
                            const float* __restrict__ g2, const float* __restrict__ be2,
                            float* __restrict__ out) {
    int i = blockIdx.x * blockDim.x + threadIdx.x;  // 1024*8
    int g = i >> 3, o = i & 7;
    float acc = 0.f;
#pragma unroll
    for (int k = 0; k < 32; k++) {
        float x = d_y2[g * 32 + k];
        x = fmaxf((x - d_stat2[k]) * d_stat2[32 + k] * g2[k] + be2[k], 0.f);
        acc += x * Wf3[k * 8 + o];
    }
    out[i] = acc + bf3[o];
}

extern "C" void kernel_launch(void* const* d_in, const int* in_sizes, int n_in,
                              void* d_out, int out_size) {
    const float* feat = (const float*)d_in[0];
    const float* sf   = (const float*)d_in[1];
    const int*   src  = (const int*)d_in[2];
    const int*   dst  = (const int*)d_in[3];
    const int*   n2g  = (const int*)d_in[4];
    const float* W1   = (const float*)d_in[5];
    const float* b1   = (const float*)d_in[6];
    const float* W2   = (const float*)d_in[7];
    const float* b2   = (const float*)d_in[8];
    const float* Wf1  = (const float*)d_in[9];
    const float* bf1  = (const float*)d_in[10];
    const float* g1   = (const float*)d_in[11];
    const float* be1  = (const float*)d_in[12];
    const float* Wf2  = (const float*)d_in[13];
    const float* bf2  = (const float*)d_in[14];
    const float* g2   = (const float*)d_in[15];
    const float* be2  = (const float*)d_in[16];
    const float* Wf3  = (const float*)d_in[17];
    const float* bf3  = (const float*)d_in[18];
    float* out = (float*)d_out;

    // CSR build + projections, ordered so proj1 is launch #4 (ncu slot)
    zero_kernel<<<512, 256>>>();                                   // 1
    deg_kernel<<<(NE + 255) / 256, 256>>>(dst);                    // 2
    scan_kernel<<<1, 1024>>>();                                    // 3
    proj_kernel<100, 25, 8, 16, 32, 1><<<(NN + 127) / 128, 25 * 8>>>(feat, W1, NN, 128);  // 4
    fill_kernel<<<(NE + 255) / 256, 256>>>(src, dst);              // 5
    gather1_kernel<<<(NN * 25 + 255) / 256, 256>>>(b1);            // 6

    proj_kernel<20, 5, 32, 16, 20, 2><<<(NN + 511) / 512, 5 * 32>>>(feat, W2, NN, 100);
    gather2_kernel<<<(NN * 5 + 255) / 256, 256>>>(b2, n2g);

    // MLP head
    mlp1_kernel<<<NG / 16, 128>>>(sf, Wf1, bf1);
    bnstats_kernel<128><<<128, 256>>>();
    mlp2_kernel<<<NG * 32 / 256, 256>>>(Wf2, bf2, g1, be1);
    bnstats_kernel<32><<<32, 256>>>();
    mlp3_kernel<<<NG * 8 / 256, 256>>>(Wf3, bf3, g2, be2, out);
}

// round 4
// speedup vs baseline: 1.7822x; 1.7822x over previous
#include <cuda_runtime.h>
#include <cuda_bf16.h>

// Net_12403865551680 — 2-layer GCN + mean-pool + Kronecker BN-MLP head.
// R3: 631 us. proj1 measured 108.9 us @ occ 19%, fma 37%.
// R4: proj1 re-tiled for 50% occ; hp1 messages in bf16 (fp32 accum);
//     proj2 thread-per-node f32x2; 3-phase parallel scan; mlp1 f32x2.

typedef unsigned long long ull;

#define NN 100000
#define NE 1600000
#define NG 1024

struct __align__(8) bf4 { __nv_bfloat162 a, b; };

// ---------------- scratch ----------------
__device__ __align__(128) bf4   d_hp1b[NN * 25];   // feat@W1, bf16, 100 dims/node
__device__ __align__(128) float d_h1[NN * 100];    // relu(agg(hp1)/deg + b1)
__device__ __align__(128) float d_hp2[NN * 20];    // h1@W2
__device__ int   d_deg[NN];
__device__ int   d_bsum[98];
__device__ int   d_boff[98];
__device__ int   d_rowstart[NN + 1];
__device__ int   d_cursor[NN];
__device__ int   d_csr[NE];
__device__ __align__(128) float d_gsum[NG * 20];
__device__ float d_gcnt[NG];
__device__ __align__(128) float d_y1[NG * 128];
__device__ __align__(128) float d_y2[NG * 32];
__device__ float d_stat1[2 * 128];
__device__ float d_stat2[2 * 32];

// ---------------- packed f32x2 helpers ----------------
__device__ __forceinline__ ull dup2(float x) {
    ull r; asm("mov.b64 %0, {%1, %1};" : "=l"(r) : "f"(x)); return r;
}
__device__ __forceinline__ ull pk2(float lo, float hi) {
    ull r; asm("mov.b64 %0, {%1, %2};" : "=l"(r) : "f"(lo), "f"(hi)); return r;
}
__device__ __forceinline__ void fma2(ull& d, ull a, ull b) {
    asm("fma.rn.f32x2 %0, %1, %2, %0;" : "+l"(d) : "l"(a), "l"(b));
}
__device__ __forceinline__ float f2lo(ull v) { return __uint_as_float((unsigned)v); }
__device__ __forceinline__ float f2hi(ull v) { return __uint_as_float((unsigned)(v >> 32)); }

// ---------------- zero accumulators ----------------
__global__ void zero_kernel() {
    int i = blockIdx.x * blockDim.x + threadIdx.x;
    int st = gridDim.x * blockDim.x;
    for (int j = i; j < NN; j += st) d_deg[j] = 0;
    for (int j = i; j < NG * 20; j += st) d_gsum[j] = 0.f;
    for (int j = i; j < NG; j += st) d_gcnt[j] = 0.f;
}

// ---------------- degree histogram ----------------
__global__ void deg_kernel(const int* __restrict__ dst) {
    int i = blockIdx.x * blockDim.x + threadIdx.x;
    if (i < NE) atomicAdd(&d_deg[dst[i]], 1);
}

// ---------------- scan phase A: per-block sums (98 blocks x 1024) ----------------
__global__ void __launch_bounds__(1024) sumA_kernel() {
    int b = blockIdx.x;
    int t = threadIdx.x;
    int i = b * 1024 + t;
    int v = (i < NN) ? d_deg[i] : 0;
#pragma unroll
    for (int o = 16; o > 0; o >>= 1) v += __shfl_down_sync(0xffffffffu, v, o);
    __shared__ int ws[32];
    if ((t & 31) == 0) ws[t >> 5] = v;
    __syncthreads();
    if (t < 32) {
        int s = ws[t];
#pragma unroll
        for (int o = 16; o > 0; o >>= 1) s += __shfl_down_sync(0xffffffffu, s, o);
        if (t == 0) d_bsum[b] = s;
    }
}

// ---------------- scan phase B: tiny serial scan of 98 block sums ----------------
__global__ void scanB_kernel() {
    if (threadIdx.x == 0) {
        int run = 0;
        for (int b = 0; b < 98; b++) { d_boff[b] = run; run += d_bsum[b]; }
        d_rowstart[NN] = NE;
    }
}

// ---------------- scan phase C: local exclusive scan + offset ----------------
__global__ void __launch_bounds__(1024) scanC_kernel() {
    int b = blockIdx.x;
    int t = threadIdx.x;
    int i = b * 1024 + t;
    int v = (i < NN) ? d_deg[i] : 0;
    int lane = t & 31, w = t >> 5;
    int inc = v;
#pragma unroll
    for (int o = 1; o < 32; o <<= 1) {
        int u = __shfl_up_sync(0xffffffffu, inc, o);
        if (lane >= o) inc += u;
    }
    __shared__ int ws[32];
    if (lane == 31) ws[w] = inc;
    __syncthreads();
    if (w == 0) {
        int x = ws[lane];
#pragma unroll
        for (int o = 1; o < 32; o <<= 1) {
            int u = __shfl_up_sync(0xffffffffu, x, o);
            if (lane >= o) x += u;
        }
        ws[lane] = x;
    }
    __syncthreads();
    int excl = inc - v + (w > 0 ? ws[w - 1] : 0) + d_boff[b];
    if (i < NN) {
        d_rowstart[i] = excl;
        d_cursor[i] = excl;
    }
}

// ---------------- CSR fill ----------------
__global__ void fill_kernel(const int* __restrict__ src, const int* __restrict__ dst) {
    int e = blockIdx.x * blockDim.x + threadIdx.x;
    if (e >= NE) return;
    int d = dst[e];
    int p = atomicAdd(&d_cursor[d], 1);
    d_csr[p] = src[e];
}

// ---------------- proj1: hp1(bf16) = feat[NN,128] @ W1[128,100] ----------------
// 256 threads: 250 active as (ot 0..24) x (nt 0..9); 8 nodes/thread (4 f32x2 pairs)
// node tile 80, grid 1250 (exact).
__global__ void __launch_bounds__(256) proj1_kernel(const float* __restrict__ X,
                                                    const float* __restrict__ W1) {
    constexpr int KC = 32, XSS = 84, NODE_TILE = 80;
    __shared__ float Xs[KC * XSS];
    __shared__ float Ws[KC * 100];
    int tid = threadIdx.x;
    int ot = tid % 25;
    int nt = tid / 25;              // 0..10; nt==10 -> inactive for compute
    bool act = tid < 250;
    int nodeBase = blockIdx.x * NODE_TILE;

    ull acc[4][4];
#pragma unroll
    for (int i = 0; i < 4; i++) { acc[i][0] = 0; acc[i][1] = 0; acc[i][2] = 0; acc[i][3] = 0; }

    for (int kc0 = 0; kc0 < 128; kc0 += KC) {
        __syncthreads();
        for (int idx = tid; idx < KC * NODE_TILE; idx += 256) {
            int k = idx % KC;
            int n = idx / KC;
            Xs[k * XSS + n] = X[(nodeBase + n) * 128 + kc0 + k];
        }
        for (int idx = tid; idx < KC * 100; idx += 256) {
            Ws[idx] = W1[(kc0 + idx / 100) * 100 + idx % 100];
        }
        __syncthreads();
        if (act) {
#pragma unroll 4
            for (int k = 0; k < KC; k++) {
                float4 wv = *(const float4*)&Ws[k * 100 + ot * 4];
                ull w0 = dup2(wv.x), w1 = dup2(wv.y), w2 = dup2(wv.z), w3 = dup2(wv.w);
#pragma unroll
                for (int i = 0; i < 4; i++) {
                    ull a = *(const ull*)&Xs[k * XSS + nt * 8 + 2 * i];
                    fma2(acc[i][0], a, w0);
                    fma2(acc[i][1], a, w1);
                    fma2(acc[i][2], a, w2);
                    fma2(acc[i][3], a, w3);
                }
            }
        }
    }
    if (act) {
#pragma unroll
        for (int i = 0; i < 4; i++) {
            int n0 = nodeBase + nt * 8 + 2 * i;
            bf4 lo, hi;
            lo.a = __floats2bfloat162_rn(f2lo(acc[i][0]), f2lo(acc[i][1]));
            lo.b = __floats2bfloat162_rn(f2lo(acc[i][2]), f2lo(acc[i][3]));
            hi.a = __floats2bfloat162_rn(f2hi(acc[i][0]), f2hi(acc[i][1]));
            hi.b = __floats2bfloat162_rn(f2hi(acc[i][2]), f2hi(acc[i][3]));
            d_hp1b[n0 * 25 + ot] = lo;
            d_hp1b[(n0 + 1) * 25 + ot] = hi;
        }
    }
}

// ---------------- layer-1 gather: bf16 messages, fp32 accum ----------------
__global__ void __launch_bounds__(256) gather1_kernel(const float* __restrict__ b1) {
    int i = blockIdx.x * 256 + threadIdx.x;
    if (i >= NN * 25) return;
    int n = i / 25;
    int c = i - n * 25;
    int row0 = d_rowstart[n];
    int row1 = d_rowstart[n + 1];
    int deg = row1 - row0;

    float4 a0 = make_float4(0.f, 0.f, 0.f, 0.f);
    float4 a1 = make_float4(0.f, 0.f, 0.f, 0.f);
    int j = row0;
    for (; j + 1 < row1; j += 2) {
        int s0 = __ldg(&d_csr[j]);
        int s1 = __ldg(&d_csr[j + 1]);
        bf4 v0 = d_hp1b[s0 * 25 + c];
        bf4 v1 = d_hp1b[s1 * 25 + c];
        float2 f0a = __bfloat1622float2(v0.a), f0b = __bfloat1622float2(v0.b);
        float2 f1a = __bfloat1622float2(v1.a), f1b = __bfloat1622float2(v1.b);
        a0.x += f0a.x; a0.y += f0a.y; a0.z += f0b.x; a0.w += f0b.y;
        a1.x += f1a.x; a1.y += f1a.y; a1.z += f1b.x; a1.w += f1b.y;
    }
    if (j < row1) {
        int s = __ldg(&d_csr[j]);
        bf4 v = d_hp1b[s * 25 + c];
        float2 fa = __bfloat1622float2(v.a), fb = __bfloat1622float2(v.b);
        a0.x += fa.x; a0.y += fa.y; a0.z += fb.x; a0.w += fb.y;
    }
    float4 v;
    if (deg > 0) {
        float inv = 1.f / (float)deg;
        v = make_float4((a0.x + a1.x) * inv, (a0.y + a1.y) * inv,
                        (a0.z + a1.z) * inv, (a0.w + a1.w) * inv);
    } else {
        bf4 sv = d_hp1b[n * 25 + c];
        float2 fa = __bfloat1622float2(sv.a), fb = __bfloat1622float2(sv.b);
        v = make_float4(fa.x, fa.y, fb.x, fb.y);
    }
    float4 b = *(const float4*)(b1 + c * 4);
    float4 r = make_float4(fmaxf(v.x + b.x, 0.f), fmaxf(v.y + b.y, 0.f),
                           fmaxf(v.z + b.z, 0.f), fmaxf(v.w + b.w, 0.f));
    *(float4*)(d_h1 + n * 100 + c * 4) = r;
}

// ---------------- proj2: hp2 = h1[NN,100] @ W2[100,20], thread-per-node ----------------
__global__ void __launch_bounds__(256) proj2_kernel(const float* __restrict__ W2) {
    constexpr int KC = 25, XSS = 260;
    __shared__ float Xs[KC * XSS];
    __shared__ ull W2d[100 * 10];
    int tid = threadIdx.x;
    int nodeBase = blockIdx.x * 256;
    int n = nodeBase + tid;

    for (int idx = tid; idx < 1000; idx += 256) {
        int k = idx / 10, p = idx % 10;
        W2d[idx] = pk2(W2[k * 20 + 2 * p], W2[k * 20 + 2 * p + 1]);
    }

    ull acc[10];
#pragma unroll
    for (int p = 0; p < 10; p++) acc[p] = 0;

    for (int kc0 = 0; kc0 < 100; kc0 += KC) {
        __syncthreads();
        for (int idx = tid; idx < KC * 256; idx += 256) {
            int nl = idx / KC;
            int k = idx % KC;
            int gn = nodeBase + nl;
            Xs[k * XSS + nl] = (gn < NN) ? d_h1[gn * 100 + kc0 + k] : 0.f;
        }
        __syncthreads();
#pragma unroll 5
        for (int k = 0; k < KC; k++) {
            ull a = dup2(Xs[k * XSS + tid]);
            const ull* wr = &W2d[(kc0 + k) * 10];
#pragma unroll
            for (int p = 0; p < 10; p++) fma2(acc[p], a, wr[p]);
        }
    }
    if (n < NN) {
#pragma unroll
        for (int q = 0; q < 5; q++) {
            float4 r = make_float4(f2lo(acc[2 * q]), f2hi(acc[2 * q]),
                                   f2lo(acc[2 * q + 1]), f2hi(acc[2 * q + 1]));
            *(float4*)(d_hp2 + n * 20 + q * 4) = r;
        }
    }
}

// ---------------- layer-2 gather + fused graph pooling ----------------
__global__ void __launch_bounds__(256) gather2_kernel(const float* __restrict__ b2,
                                                      const int* __restrict__ n2g) {
    int i = blockIdx.x * 256 + threadIdx.x;
    if (i >= NN * 5) return;
    int n = i / 5;
    int c = i - n * 5;
    int row0 = d_rowstart[n];
    int row1 = d_rowstart[n + 1];
    int deg = row1 - row0;

    float4 a0 = make_float4(0.f, 0.f, 0.f, 0.f);
    float4 a1 = make_float4(0.f, 0.f, 0.f, 0.f);
    int j = row0;
    for (; j + 1 < row1; j += 2) {
        int s0 = __ldg(&d_csr[j]);
        int s1 = __ldg(&d_csr[j + 1]);
        float4 f0 = *(const float4*)(d_hp2 + s0 * 20 + c * 4);
        float4 f1 = *(const float4*)(d_hp2 + s1 * 20 + c * 4);
        a0.x += f0.x; a0.y += f0.y; a0.z += f0.z; a0.w += f0.w;
        a1.x += f1.x; a1.y += f1.y; a1.z += f1.z; a1.w += f1.w;
    }
    if (j < row1) {
        int s = __ldg(&d_csr[j]);
        float4 f = *(const float4*)(d_hp2 + s * 20 + c * 4);
        a0.x += f.x; a0.y += f.y; a0.z += f.z; a0.w += f.w;
    }
    float4 v;
    if (deg > 0) {
        float inv = 1.f / (float)deg;
        v = make_float4((a0.x + a1.x) * inv, (a0.y + a1.y) * inv,
                        (a0.z + a1.z) * inv, (a0.w + a1.w) * inv);
    } else {
        v = *(const float4*)(d_hp2 + n * 20 + c * 4);
    }
    float4 b = *(const float4*)(b2 + c * 4);
    float4 r = make_float4(fmaxf(v.x + b.x, 0.f), fmaxf(v.y + b.y, 0.f),
                           fmaxf(v.z + b.z, 0.f), fmaxf(v.w + b.w, 0.f));
    int g = n2g[n];
    float* gs = d_gsum + g * 20 + c * 4;
    atomicAdd(gs + 0, r.x);
    atomicAdd(gs + 1, r.y);
    atomicAdd(gs + 2, r.z);
    atomicAdd(gs + 3, r.w);
    if (c == 0) atomicAdd(&d_gcnt[g], 1.f);
}

// ---------------- mlp1: y1 = (hg (x) sf) @ Wf1 + bf1, f32x2 over graph pairs ----------------
__global__ void __launch_bounds__(128) mlp1_kernel(const float* __restrict__ sf,
                                                   const float* __restrict__ Wf1,
                                                   const float* __restrict__ bf1) {
    __shared__ float fs[640 * 8];       // [j][g], g pairs read as f32x2
    int g0 = blockIdx.x * 8;
    int tid = threadIdx.x;
    for (int idx = tid; idx < 640 * 8; idx += 128) {
        int j = idx >> 3;
        int g = idx & 7;
        int k = j >> 5, s = j & 31;
        float inv = 1.f / fmaxf(d_gcnt[g0 + g], 1.f);
        fs[idx] = d_gsum[(g0 + g) * 20 + k] * inv * sf[(g0 + g) * 32 + s];
    }
    __syncthreads();
    int o = tid;
    ull acc[4] = {0, 0, 0, 0};
#pragma unroll 4
    for (int j = 0; j < 640; j++) {
        ull wd = dup2(Wf1[j * 128 + o]);
#pragma unroll
        for (int p = 0; p < 4; p++) {
            ull a = *(const ull*)&fs[j * 8 + 2 * p];
            fma2(acc[p], a, wd);
        }
    }
    float b = bf1[o];
#pragma unroll
    for (int p = 0; p < 4; p++) {
        d_y1[(g0 + 2 * p) * 128 + o] = f2lo(acc[p]) + b;
        d_y1[(g0 + 2 * p + 1) * 128 + o] = f2hi(acc[p]) + b;
    }
}

// ---------------- BatchNorm stats ----------------
template<int C>
__global__ void bnstats_kernel() {
    const float* __restrict__ Y = (C == 128) ? (const float*)d_y1 : (const float*)d_y2;
    float* __restrict__ stat = (C == 128) ? d_stat1 : d_stat2;
    int c = blockIdx.x;
    float s = 0.f, q = 0.f;
    for (int r = threadIdx.x; r < NG; r += 256) {
        float x = Y[r * C + c];
        s += x; q += x * x;
    }
#pragma unroll
    for (int o = 16; o > 0; o >>= 1) {
        s += __shfl_down_sync(0xffffffff, s, o);
        q += __shfl_down_sync(0xffffffff, q, o);
    }
    __shared__ float ss[8], sq[8];
    int w = threadIdx.x >> 5, l = threadIdx.x & 31;
    if (l == 0) { ss[w] = s; sq[w] = q; }
    __syncthreads();
    if (threadIdx.x == 0) {
        float S = 0.f, Q = 0.f;
#pragma unroll
        for (int i = 0; i < 8; i++) { S += ss[i]; Q += sq[i]; }
        float mu = S / (float)NG;
        float var = Q / (float)NG - mu * mu;
        stat[c] = mu;
        stat[C + c] = rsqrtf(var + 1e-5f);
    }
}

// ---------------- mlp2 ----------------
__global__ void mlp2_kernel(const float* __restrict__ Wf2, const float* __restrict__ bf2,
                            const float* __restrict__ g1, const float* __restrict__ be1) {
    int i = blockIdx.x * blockDim.x + threadIdx.x;
    int g = i >> 5, o = i & 31;
    float acc = 0.f;
    for (int k = 0; k < 128; k++) {
        float x = d_y1[g * 128 + k];
        x = fmaxf((x - d_stat1[k]) * d_stat1[128 + k] * g1[k] + be1[k], 0.f);
        acc += x * Wf2[k * 32 + o];
    }
    d_y2[g * 32 + o] = acc + bf2[o];
}

// ---------------- mlp3 ----------------
__global__ void mlp3_kernel(const float* __restrict__ Wf3, const float* __restrict__ bf3,
                            const float* __restrict__ g2, const float* __restrict__ be2,
                            float* __restrict__ out) {
    int i = blockIdx.x * blockDim.x + threadIdx.x;
    int g = i >> 3, o = i & 7;
    float acc = 0.f;
#pragma unroll
    for (int k = 0; k < 32; k++) {
        float x = d_y2[g * 32 + k];
        x = fmaxf((x - d_stat2[k]) * d_stat2[32 + k] * g2[k] + be2[k], 0.f);
        acc += x * Wf3[k * 8 + o];
    }
    out[i] = acc + bf3[o];
}

extern "C" void kernel_launch(void* const* d_in, const int* in_sizes, int n_in,
                              void* d_out, int out_size) {
    const float* feat = (const float*)d_in[0];
    const float* sf   = (const float*)d_in[1];
    const int*   src  = (const int*)d_in[2];
    const int*   dst  = (const int*)d_in[3];
    const int*   n2g  = (const int*)d_in[4];
    const float* W1   = (const float*)d_in[5];
    const float* b1   = (const float*)d_in[6];
    const float* W2   = (const float*)d_in[7];
    const float* b2   = (const float*)d_in[8];
    const float* Wf1  = (const float*)d_in[9];
    const float* bf1  = (const float*)d_in[10];
    const float* g1   = (const float*)d_in[11];
    const float* be1  = (const float*)d_in[12];
    const float* Wf2  = (const float*)d_in[13];
    const float* bf2  = (const float*)d_in[14];
    const float* g2   = (const float*)d_in[15];
    const float* be2  = (const float*)d_in[16];
    const float* Wf3  = (const float*)d_in[17];
    const float* bf3  = (const float*)d_in[18];
    float* out = (float*)d_out;

    zero_kernel<<<512, 256>>>();                                   // 1
    deg_kernel<<<(NE + 255) / 256, 256>>>(dst);                    // 2
    sumA_kernel<<<98, 1024>>>();                                   // 3
    proj1_kernel<<<1250, 256>>>(feat, W1);                         // 4  (ncu slot)
    scanB_kernel<<<1, 32>>>();                                     // 5
    scanC_kernel<<<98, 1024>>>();                                  // 6
    fill_kernel<<<(NE + 255) / 256, 256>>>(src, dst);              // 7
    gather1_kernel<<<(NN * 25 + 255) / 256, 256>>>(b1);            // 8
    proj2_kernel<<<(NN + 255) / 256, 256>>>(W2);                   // 9
    gather2_kernel<<<(NN * 5 + 255) / 256, 256>>>(b2, n2g);        // 10

    mlp1_kernel<<<NG / 8, 128>>>(sf, Wf1, bf1);                    // 11
    bnstats_kernel<128><<<128, 256>>>();                           // 12
    mlp2_kernel<<<NG * 32 / 256, 256>>>(Wf2, bf2, g1, be1);        // 13
    bnstats_kernel<32><<<32, 256>>>();                             // 14
    mlp3_kernel<<<NG * 8 / 256, 256>>>(Wf3, bf3, g2, be2, out);    // 15
}

// round 6
// speedup vs baseline: 1.9907x; 1.1170x over previous
#include <cuda_runtime.h>
#include <cuda_bf16.h>
#include <mma.h>

// Net_12403865551680 — 2-layer GCN + mean-pool + Kronecker BN-MLP head.
// R4: 354 us (best). R5: wmma proj1 FAILED — Cs leading dim 104 < 112 needed
// by the n=6 tile -> smem overflow corrupting adjacent rows (rel_err 6e-2).
// R6: fix Cs ld to 112. Everything else identical to R5.

using namespace nvcuda;

typedef unsigned long long ull;

#define NN 100000
#define NE 1600000
#define NG 1024

struct __align__(8) bf4 { __nv_bfloat162 a, b; };

// ---------------- scratch ----------------
__device__ __align__(128) bf4   d_hp1b[NN * 25];   // feat@W1, bf16, 100 dims/node
__device__ __align__(128) float d_h1[NN * 100];    // relu(agg(hp1)/deg + b1)
__device__ __align__(128) float d_hp2[NN * 20];    // h1@W2
__device__ int   d_deg[NN];
__device__ int   d_bsum[98];
__device__ int   d_boff[98];
__device__ int   d_rowstart[NN + 1];
__device__ int   d_cursor[NN];
__device__ int   d_csr[NE];
__device__ __align__(128) float d_gsum[NG * 20];
__device__ float d_gcnt[NG];
__device__ __align__(128) float d_y1[NG * 128];
__device__ __align__(128) float d_y2[NG * 32];
__device__ float d_stat1[2 * 128];
__device__ float d_stat2[2 * 32];

// ---------------- packed f32x2 helpers ----------------
__device__ __forceinline__ ull dup2(float x) {
    ull r; asm("mov.b64 %0, {%1, %1};" : "=l"(r) : "f"(x)); return r;
}
__device__ __forceinline__ ull pk2(float lo, float hi) {
    ull r; asm("mov.b64 %0, {%1, %2};" : "=l"(r) : "f"(lo), "f"(hi)); return r;
}
__device__ __forceinline__ void fma2(ull& d, ull a, ull b) {
    asm("fma.rn.f32x2 %0, %1, %2, %0;" : "+l"(d) : "l"(a), "l"(b));
}
__device__ __forceinline__ float f2lo(ull v) { return __uint_as_float((unsigned)v); }
__device__ __forceinline__ float f2hi(ull v) { return __uint_as_float((unsigned)(v >> 32)); }

// ---------------- zero accumulators ----------------
__global__ void zero_kernel() {
    int i = blockIdx.x * blockDim.x + threadIdx.x;
    int st = gridDim.x * blockDim.x;
    for (int j = i; j < NN; j += st) d_deg[j] = 0;
    for (int j = i; j < NG * 20; j += st) d_gsum[j] = 0.f;
    for (int j = i; j < NG; j += st) d_gcnt[j] = 0.f;
}

// ---------------- degree histogram ----------------
__global__ void deg_kernel(const int* __restrict__ dst) {
    int i = blockIdx.x * blockDim.x + threadIdx.x;
    if (i < NE) atomicAdd(&d_deg[dst[i]], 1);
}

// ---------------- scan phase A: per-block sums ----------------
__global__ void __launch_bounds__(1024) sumA_kernel() {
    int b = blockIdx.x;
    int t = threadIdx.x;
    int i = b * 1024 + t;
    int v = (i < NN) ? d_deg[i] : 0;
#pragma unroll
    for (int o = 16; o > 0; o >>= 1) v += __shfl_down_sync(0xffffffffu, v, o);
    __shared__ int ws[32];
    if ((t & 31) == 0) ws[t >> 5] = v;
    __syncthreads();
    if (t < 32) {
        int s = ws[t];
#pragma unroll
        for (int o = 16; o > 0; o >>= 1) s += __shfl_down_sync(0xffffffffu, s, o);
        if (t == 0) d_bsum[b] = s;
    }
}

// ---------------- scan phase B ----------------
__global__ void scanB_kernel() {
    if (threadIdx.x == 0) {
        int run = 0;
        for (int b = 0; b < 98; b++) { d_boff[b] = run; run += d_bsum[b]; }
        d_rowstart[NN] = NE;
    }
}

// ---------------- scan phase C ----------------
__global__ void __launch_bounds__(1024) scanC_kernel() {
    int b = blockIdx.x;
    int t = threadIdx.x;
    int i = b * 1024 + t;
    int v = (i < NN) ? d_deg[i] : 0;
    int lane = t & 31, w = t >> 5;
    int inc = v;
#pragma unroll
    for (int o = 1; o < 32; o <<= 1) {
        int u = __shfl_up_sync(0xffffffffu, inc, o);
        if (lane >= o) inc += u;
    }
    __shared__ int ws[32];
    if (lane == 31) ws[w] = inc;
    __syncthreads();
    if (w == 0) {
        int x = ws[lane];
#pragma unroll
        for (int o = 1; o < 32; o <<= 1) {
            int u = __shfl_up_sync(0xffffffffu, x, o);
            if (lane >= o) x += u;
        }
        ws[lane] = x;
    }
    __syncthreads();
    int excl = inc - v + (w > 0 ? ws[w - 1] : 0) + d_boff[b];
    if (i < NN) {
        d_rowstart[i] = excl;
        d_cursor[i] = excl;
    }
}

// ---------------- CSR fill ----------------
__global__ void fill_kernel(const int* __restrict__ src, const int* __restrict__ dst) {
    int e = blockIdx.x * blockDim.x + threadIdx.x;
    if (e >= NE) return;
    int d = dst[e];
    int p = atomicAdd(&d_cursor[d], 1);
    d_csr[p] = src[e];
}

// ---------------- proj1 (tensor cores): hp1(bf16) = feat[NN,128] @ W1[128,100] ----------------
// Block: 128-row M tile, N padded to 112 (7 wmma n-tiles), K=128 in smem.
// 8 warps x (16 rows x 112 cols). Dynamic smem 65536 B:
//   As bf16[128][136] (34816 B) | Bs bf16[128][120] (30720 B);
//   Cs float[128][112] (57344 B) reuses the same buffer after a sync.
__global__ void __launch_bounds__(256) proj1_kernel(const float* __restrict__ X,
                                                    const float* __restrict__ W1) {
    extern __shared__ char smraw[];
    __nv_bfloat16* As = (__nv_bfloat16*)smraw;            // ld 136
    __nv_bfloat16* Bs = (__nv_bfloat16*)(smraw + 34816);  // ld 120
    float* Cs = (float*)smraw;                            // ld 112 (reuse)
    const int tid = threadIdx.x;
    const int wid = tid >> 5;
    const int mBase = blockIdx.x * 128;

    // A: fp32 -> bf16, coalesced float2 loads
    for (int idx = tid; idx < 128 * 64; idx += 256) {
        int r = idx >> 6;
        int c2 = idx & 63;
        int gn = mBase + r;
        float2 v = (gn < NN) ? *(const float2*)(X + gn * 128 + 2 * c2)
                             : make_float2(0.f, 0.f);
        *(__nv_bfloat162*)(As + r * 136 + 2 * c2) = __floats2bfloat162_rn(v.x, v.y);
    }
    // B: W1[128][100] -> bf16, cols 100..111 zero
    for (int idx = tid; idx < 128 * 112; idx += 256) {
        int k = idx / 112;
        int n = idx - k * 112;
        Bs[k * 120 + n] = __float2bfloat16((n < 100) ? W1[k * 100 + n] : 0.f);
    }
    __syncthreads();

    wmma::fragment<wmma::accumulator, 16, 16, 16, float> c[7];
#pragma unroll
    for (int n = 0; n < 7; n++) wmma::fill_fragment(c[n], 0.f);
#pragma unroll
    for (int k = 0; k < 8; k++) {
        wmma::fragment<wmma::matrix_a, 16, 16, 16, __nv_bfloat16, wmma::row_major> a;
        wmma::load_matrix_sync(a, As + (wid * 16) * 136 + k * 16, 136);
#pragma unroll
        for (int n = 0; n < 7; n++) {
            wmma::fragment<wmma::matrix_b, 16, 16, 16, __nv_bfloat16, wmma::row_major> b;
            wmma::load_matrix_sync(b, Bs + (k * 16) * 120 + n * 16, 120);
            wmma::mma_sync(c[n], a, b, c[n]);
        }
    }
    __syncthreads();   // all warps done reading As/Bs before Cs overwrite
#pragma unroll
    for (int n = 0; n < 7; n++)
        wmma::store_matrix_sync(Cs + (wid * 16) * 112 + n * 16, c[n], 112, wmma::mem_row_major);
    __syncthreads();

    // Cs -> d_hp1b (bf16 x4 chunks), 100 valid cols
    for (int idx = tid; idx < 128 * 25; idx += 256) {
        int r = idx / 25;
        int cc = idx - r * 25;
        int gn = mBase + r;
        if (gn < NN) {
            const float* p = Cs + r * 112 + cc * 4;
            bf4 o;
            o.a = __floats2bfloat162_rn(p[0], p[1]);
            o.b = __floats2bfloat162_rn(p[2], p[3]);
            d_hp1b[gn * 25 + cc] = o;
        }
    }
}

// ---------------- layer-1 gather: bf16 messages, fp32 accum ----------------
__global__ void __launch_bounds__(256) gather1_kernel(const float* __restrict__ b1) {
    int i = blockIdx.x * 256 + threadIdx.x;
    if (i >= NN * 25) return;
    int n = i / 25;
    int c = i - n * 25;
    int row0 = d_rowstart[n];
    int row1 = d_rowstart[n + 1];
    int deg = row1 - row0;

    float4 a0 = make_float4(0.f, 0.f, 0.f, 0.f);
    float4 a1 = make_float4(0.f, 0.f, 0.f, 0.f);
    int j = row0;
    for (; j + 1 < row1; j += 2) {
        int s0 = __ldg(&d_csr[j]);
        int s1 = __ldg(&d_csr[j + 1]);
        bf4 v0 = d_hp1b[s0 * 25 + c];
        bf4 v1 = d_hp1b[s1 * 25 + c];
        float2 f0a = __bfloat1622float2(v0.a), f0b = __bfloat1622float2(v0.b);
        float2 f1a = __bfloat1622float2(v1.a), f1b = __bfloat1622float2(v1.b);
        a0.x += f0a.x; a0.y += f0a.y; a0.z += f0b.x; a0.w += f0b.y;
        a1.x += f1a.x; a1.y += f1a.y; a1.z += f1b.x; a1.w += f1b.y;
    }
    if (j < row1) {
        int s = __ldg(&d_csr[j]);
        bf4 v = d_hp1b[s * 25 + c];
        float2 fa = __bfloat1622float2(v.a), fb = __bfloat1622float2(v.b);
        a0.x += fa.x; a0.y += fa.y; a0.z += fb.x; a0.w += fb.y;
    }
    float4 v;
    if (deg > 0) {
        float inv = 1.f / (float)deg;
        v = make_float4((a0.x + a1.x) * inv, (a0.y + a1.y) * inv,
                        (a0.z + a1.z) * inv, (a0.w + a1.w) * inv);
    } else {
        bf4 sv = d_hp1b[n * 25 + c];
        float2 fa = __bfloat1622float2(sv.a), fb = __bfloat1622float2(sv.b);
        v = make_float4(fa.x, fa.y, fb.x, fb.y);
    }
    float4 b = *(const float4*)(b1 + c * 4);
    float4 r = make_float4(fmaxf(v.x + b.x, 0.f), fmaxf(v.y + b.y, 0.f),
                           fmaxf(v.z + b.z, 0.f), fmaxf(v.w + b.w, 0.f));
    *(float4*)(d_h1 + n * 100 + c * 4) = r;
}

// ---------------- proj2: hp2 = h1[NN,100] @ W2[100,20], thread-per-node f32x2 ----------------
__global__ void __launch_bounds__(256) proj2_kernel(const float* __restrict__ W2) {
    constexpr int KC = 25, XSS = 260;
    __shared__ float Xs[KC * XSS];
    __shared__ ull W2d[100 * 10];
    int tid = threadIdx.x;
    int nodeBase = blockIdx.x * 256;
    int n = nodeBase + tid;

    for (int idx = tid; idx < 1000; idx += 256) {
        int k = idx / 10, p = idx % 10;
        W2d[idx] = pk2(W2[k * 20 + 2 * p], W2[k * 20 + 2 * p + 1]);
    }

    ull acc[10];
#pragma unroll
    for (int p = 0; p < 10; p++) acc[p] = 0;

    for (int kc0 = 0; kc0 < 100; kc0 += KC) {
        __syncthreads();
        for (int idx = tid; idx < KC * 256; idx += 256) {
            int nl = idx / KC;
            int k = idx % KC;
            int gn = nodeBase + nl;
            Xs[k * XSS + nl] = (gn < NN) ? d_h1[gn * 100 + kc0 + k] : 0.f;
        }
        __syncthreads();
#pragma unroll 5
        for (int k = 0; k < KC; k++) {
            ull a = dup2(Xs[k * XSS + tid]);
            const ull* wr = &W2d[(kc0 + k) * 10];
#pragma unroll
            for (int p = 0; p < 10; p++) fma2(acc[p], a, wr[p]);
        }
    }
    if (n < NN) {
#pragma unroll
        for (int q = 0; q < 5; q++) {
            float4 r = make_float4(f2lo(acc[2 * q]), f2hi(acc[2 * q]),
                                   f2lo(acc[2 * q + 1]), f2hi(acc[2 * q + 1]));
            *(float4*)(d_hp2 + n * 20 + q * 4) = r;
        }
    }
}

// ---------------- layer-2 gather + fused graph pooling ----------------
__global__ void __launch_bounds__(256) gather2_kernel(const float* __restrict__ b2,
                                                      const int* __restrict__ n2g) {
    int i = blockIdx.x * 256 + threadIdx.x;
    if (i >= NN * 5) return;
    int n = i / 5;
    int c = i - n * 5;
    int row0 = d_rowstart[n];
    int row1 = d_rowstart[n + 1];
    int deg = row1 - row0;

    float4 a0 = make_float4(0.f, 0.f, 0.f, 0.f);
    float4 a1 = make_float4(0.f, 0.f, 0.f, 0.f);
    int j = row0;
    for (; j + 1 < row1; j += 2) {
        int s0 = __ldg(&d_csr[j]);
        int s1 = __ldg(&d_csr[j + 1]);
        float4 f0 = *(const float4*)(d_hp2 + s0 * 20 + c * 4);
        float4 f1 = *(const float4*)(d_hp2 + s1 * 20 + c * 4);
        a0.x += f0.x; a0.y += f0.y; a0.z += f0.z; a0.w += f0.w;
        a1.x += f1.x; a1.y += f1.y; a1.z += f1.z; a1.w += f1.w;
    }
    if (j < row1) {
        int s = __ldg(&d_csr[j]);
        float4 f = *(const float4*)(d_hp2 + s * 20 + c * 4);
        a0.x += f.x; a0.y += f.y; a0.z += f.z; a0.w += f.w;
    }
    float4 v;
    if (deg > 0) {
        float inv = 1.f / (float)deg;
        v = make_float4((a0.x + a1.x) * inv, (a0.y + a1.y) * inv,
                        (a0.z + a1.z) * inv, (a0.w + a1.w) * inv);
    } else {
        v = *(const float4*)(d_hp2 + n * 20 + c * 4);
    }
    float4 b = *(const float4*)(b2 + c * 4);
    float4 r = make_float4(fmaxf(v.x + b.x, 0.f), fmaxf(v.y + b.y, 0.f),
                           fmaxf(v.z + b.z, 0.f), fmaxf(v.w + b.w, 0.f));
    int g = n2g[n];
    float* gs = d_gsum + g * 20 + c * 4;
    atomicAdd(gs + 0, r.x);
    atomicAdd(gs + 1, r.y);
    atomicAdd(gs + 2, r.z);
    atomicAdd(gs + 3, r.w);
    if (c == 0) atomicAdd(&d_gcnt[g], 1.f);
}

// ---------------- mlp1: y1 = (hg (x) sf) @ Wf1 + bf1, f32x2 over graph pairs ----------------
__global__ void __launch_bounds__(128) mlp1_kernel(const float* __restrict__ sf,
                                                   const float* __restrict__ Wf1,
                                                   const float* __restrict__ bf1) {
    __shared__ float fs[640 * 8];
    int g0 = blockIdx.x * 8;
    int tid = threadIdx.x;
    for (int idx = tid; idx < 640 * 8; idx += 128) {
        int j = idx >> 3;
        int g = idx & 7;
        int k = j >> 5, s = j & 31;
        float inv = 1.f / fmaxf(d_gcnt[g0 + g], 1.f);
        fs[idx] = d_gsum[(g0 + g) * 20 + k] * inv * sf[(g0 + g) * 32 + s];
    }
    __syncthreads();
    int o = tid;
    ull acc[4] = {0, 0, 0, 0};
#pragma unroll 4
    for (int j = 0; j < 640; j++) {
        ull wd = dup2(Wf1[j * 128 + o]);
#pragma unroll
        for (int p = 0; p < 4; p++) {
            ull a = *(const ull*)&fs[j * 8 + 2 * p];
            fma2(acc[p], a, wd);
        }
    }
    float b = bf1[o];
#pragma unroll
    for (int p = 0; p < 4; p++) {
        d_y1[(g0 + 2 * p) * 128 + o] = f2lo(acc[p]) + b;
        d_y1[(g0 + 2 * p + 1) * 128 + o] = f2hi(acc[p]) + b;
    }
}

// ---------------- BatchNorm stats ----------------
template<int C>
__global__ void bnstats_kernel() {
    const float* __restrict__ Y = (C == 128) ? (const float*)d_y1 : (const float*)d_y2;
    float* __restrict__ stat = (C == 128) ? d_stat1 : d_stat2;
    int c = blockIdx.x;
    float s = 0.f, q = 0.f;
    for (int r = threadIdx.x; r < NG; r += 256) {
        float x = Y[r * C + c];
        s += x; q += x * x;
    }
#pragma unroll
    for (int o = 16; o > 0; o >>= 1) {
        s += __shfl_down_sync(0xffffffff, s, o);
        q += __shfl_down_sync(0xffffffff, q, o);
    }
    __shared__ float ss[8], sq[8];
    int w = threadIdx.x >> 5, l = threadIdx.x & 31;
    if (l == 0) { ss[w] = s; sq[w] = q; }
    __syncthreads();
    if (threadIdx.x == 0) {
        float S = 0.f, Q = 0.f;
#pragma unroll
        for (int i = 0; i < 8; i++) { S += ss[i]; Q += sq[i]; }
        float mu = S / (float)NG;
        float var = Q / (float)NG - mu * mu;
        stat[c] = mu;
        stat[C + c] = rsqrtf(var + 1e-5f);
    }
}

// ---------------- mlp2 ----------------
__global__ void mlp2_kernel(const float* __restrict__ Wf2, const float* __restrict__ bf2,
                            const float* __restrict__ g1, const float* __restrict__ be1) {
    int i = blockIdx.x * blockDim.x + threadIdx.x;
    int g = i >> 5, o = i & 31;
    float acc = 0.f;
    for (int k = 0; k < 128; k++) {
        float x = d_y1[g * 128 + k];
        x = fmaxf((x - d_stat1[k]) * d_stat1[128 + k] * g1[k] + be1[k], 0.f);
        acc += x * Wf2[k * 32 + o];
    }
    d_y2[g * 32 + o] = acc + bf2[o];
}

// ---------------- mlp3 ----------------
__global__ void mlp3_kernel(const float* __restrict__ Wf3, const float* __restrict__ bf3,
                            const float* __restrict__ g2, const float* __restrict__ be2,
                            float* __restrict__ out) {
    int i = blockIdx.x * blockDim.x + threadIdx.x;
    int g = i >> 3, o = i & 7;
    float acc = 0.f;
#pragma unroll
    for (int k = 0; k < 32; k++) {
        float x = d_y2[g * 32 + k];
        x = fmaxf((x - d_stat2[k]) * d_stat2[32 + k] * g2[k] + be2[k], 0.f);
        acc += x * Wf3[k * 8 + o];
    }
    out[i] = acc + bf3[o];
}

extern "C" void kernel_launch(void* const* d_in, const int* in_sizes, int n_in,
                              void* d_out, int out_size) {
    const float* feat = (const float*)d_in[0];
    const float* sf   = (const float*)d_in[1];
    const int*   src  = (const int*)d_in[2];
    const int*   dst  = (const int*)d_in[3];
    const int*   n2g  = (const int*)d_in[4];
    const float* W1   = (const float*)d_in[5];
    const float* b1   = (const float*)d_in[6];
    const float* W2   = (const float*)d_in[7];
    const float* b2   = (const float*)d_in[8];
    const float* Wf1  = (const float*)d_in[9];
    const float* bf1  = (const float*)d_in[10];
    const float* g1   = (const float*)d_in[11];
    const float* be1  = (const float*)d_in[12];
    const float* Wf2  = (const float*)d_in[13];
    const float* bf2  = (const float*)d_in[14];
    const float* g2   = (const float*)d_in[15];
    const float* be2  = (const float*)d_in[16];
    const float* Wf3  = (const float*)d_in[17];
    const float* bf3  = (const float*)d_in[18];
    float* out = (float*)d_out;

    static bool attr_set = false;
    if (!attr_set) {
        cudaFuncSetAttribute(proj1_kernel,
                             cudaFuncAttributeMaxDynamicSharedMemorySize, 65536);
        attr_set = true;
    }

    zero_kernel<<<512, 256>>>();                                   // 1
    deg_kernel<<<(NE + 255) / 256, 256>>>(dst);                    // 2
    sumA_kernel<<<98, 1024>>>();                                   // 3
    proj1_kernel<<<782, 256, 65536>>>(feat, W1);                   // 4  (ncu slot)
    scanB_kernel<<<1, 32>>>();                                     // 5
    scanC_kernel<<<98, 1024>>>();                                  // 6
    fill_kernel<<<(NE + 255) / 256, 256>>>(src, dst);              // 7
    gather1_kernel<<<(NN * 25 + 255) / 256, 256>>>(b1);            // 8
    proj2_kernel<<<(NN + 255) / 256, 256>>>(W2);                   // 9
    gather2_kernel<<<(NN * 5 + 255) / 256, 256>>>(b2, n2g);        // 10

    mlp1_kernel<<<NG / 8, 128>>>(sf, Wf1, bf1);                    // 11
    bnstats_kernel<128><<<128, 256>>>();                           // 12
    mlp2_kernel<<<NG * 32 / 256, 256>>>(Wf2, bf2, g1, be1);        // 13
    bnstats_kernel<32><<<32, 256>>>();                             // 14
    mlp3_kernel<<<NG * 8 / 256, 256>>>(Wf3, bf3, g2, be2, out);    // 15
}

// round 7
// speedup vs baseline: 2.1510x; 1.0805x over previous
#include <cuda_runtime.h>
#include <cuda_bf16.h>
#include <mma.h>

// Net_12403865551680 — 2-layer GCN + mean-pool + Kronecker BN-MLP head.
// R6: 316.9 us (proj1 48.6 us, tensor 9.5% -> staging-bound; rest = 268 us).
// R7: fuse gather1+proj2 (d_h1 eliminated), division-free proj1 staging,
//     drop zero_kernel (tail cleanup re-zeroes), merge scanB into scanC.

using namespace nvcuda;

typedef unsigned long long ull;

#define NN 100000
#define NE 1600000
#define NG 1024

struct __align__(8) bf4 { __nv_bfloat162 a, b; };

// ---------------- scratch (zero-initialized at module load) ----------------
__device__ __align__(128) bf4   d_hp1b[NN * 25];   // feat@W1, bf16, 100 dims/node
__device__ __align__(128) float d_hp2[NN * 20];    // relu(agg)+b1 projected by W2
__device__ int   d_deg[NN];                        // zeroed by cleanup each run
__device__ int   d_bsum[98];
__device__ int   d_rowstart[NN + 1];
__device__ int   d_cursor[NN];
__device__ int   d_csr[NE];
__device__ __align__(128) float d_gsum[NG * 20];   // zeroed by cleanup
__device__ float d_gcnt[NG];                       // zeroed by cleanup
__device__ __align__(128) float d_y1[NG * 128];
__device__ __align__(128) float d_y2[NG * 32];
__device__ float d_stat1[2 * 128];
__device__ float d_stat2[2 * 32];

// ---------------- packed f32x2 helpers ----------------
__device__ __forceinline__ ull dup2(float x) {
    ull r; asm("mov.b64 %0, {%1, %1};" : "=l"(r) : "f"(x)); return r;
}
__device__ __forceinline__ ull pk2(float lo, float hi) {
    ull r; asm("mov.b64 %0, {%1, %2};" : "=l"(r) : "f"(lo), "f"(hi)); return r;
}
__device__ __forceinline__ void fma2(ull& d, ull a, ull b) {
    asm("fma.rn.f32x2 %0, %1, %2, %0;" : "+l"(d) : "l"(a), "l"(b));
}
__device__ __forceinline__ float f2lo(ull v) { return __uint_as_float((unsigned)v); }
__device__ __forceinline__ float f2hi(ull v) { return __uint_as_float((unsigned)(v >> 32)); }

// ---------------- degree histogram (d_deg must be zero on entry) ----------------
__global__ void deg_kernel(const int* __restrict__ dst) {
    int i = blockIdx.x * blockDim.x + threadIdx.x;
    if (i < NE) atomicAdd(&d_deg[dst[i]], 1);
}

// ---------------- scan phase A: per-block sums (98 x 1024) ----------------
__global__ void __launch_bounds__(1024) sumA_kernel() {
    int b = blockIdx.x;
    int t = threadIdx.x;
    int i = b * 1024 + t;
    int v = (i < NN) ? d_deg[i] : 0;
#pragma unroll
    for (int o = 16; o > 0; o >>= 1) v += __shfl_down_sync(0xffffffffu, v, o);
    __shared__ int ws[32];
    if ((t & 31) == 0) ws[t >> 5] = v;
    __syncthreads();
    if (t < 32) {
        int s = ws[t];
#pragma unroll
        for (int o = 16; o > 0; o >>= 1) s += __shfl_down_sync(0xffffffffu, s, o);
        if (t == 0) d_bsum[b] = s;
    }
}

// ---------------- scan phase C: local scan; each block derives its own prefix ----------------
__global__ void __launch_bounds__(1024) scanC_kernel() {
    int b = blockIdx.x;
    int t = threadIdx.x;
    int i = b * 1024 + t;
    int v = (i < NN) ? d_deg[i] : 0;
    int lane = t & 31, w = t >> 5;
    int inc = v;
#pragma unroll
    for (int o = 1; o < 32; o <<= 1) {
        int u = __shfl_up_sync(0xffffffffu, inc, o);
        if (lane >= o) inc += u;
    }
    __shared__ int ws[32];
    __shared__ int sboff;
    if (lane == 31) ws[w] = inc;
    __syncthreads();
    if (w == 0) {
        int x = ws[lane];
#pragma unroll
        for (int o = 1; o < 32; o <<= 1) {
            int u = __shfl_up_sync(0xffffffffu, x, o);
            if (lane >= o) x += u;
        }
        ws[lane] = x;
    }
    if (w == 1) {           // concurrently: prefix over earlier blocks' sums
        int s = 0;
        for (int j = lane; j < b; j += 32) s += d_bsum[j];
#pragma unroll
        for (int o = 16; o > 0; o >>= 1) s += __shfl_down_sync(0xffffffffu, s, o);
        if (lane == 0) sboff = s;
    }
    __syncthreads();
    int excl = inc - v + (w > 0 ? ws[w - 1] : 0) + sboff;
    if (i < NN) {
        d_rowstart[i] = excl;
        d_cursor[i] = excl;
    }
    if (b == 0 && t == 0) d_rowstart[NN] = NE;
}

// ---------------- CSR fill ----------------
__global__ void fill_kernel(const int* __restrict__ src, const int* __restrict__ dst) {
    int e = blockIdx.x * blockDim.x + threadIdx.x;
    if (e >= NE) return;
    int d = dst[e];
    int p = atomicAdd(&d_cursor[d], 1);
    d_csr[p] = src[e];
}

// ---------------- proj1 (tensor cores): hp1(bf16) = feat[NN,128] @ W1[128,100] ----------------
// 128-row M tile, N padded to 112 (7 wmma n-tiles), K=128 in smem. 8 warps.
// Division-free warp/lane staging; float4 A loads.
// smem 65536: As bf16[128][136] | Bs bf16[128][120]; Cs float[128][112] reuses.
__global__ void __launch_bounds__(256) proj1_kernel(const float* __restrict__ X,
                                                    const float* __restrict__ W1) {
    extern __shared__ char smraw[];
    __nv_bfloat16* As = (__nv_bfloat16*)smraw;            // ld 136
    __nv_bfloat16* Bs = (__nv_bfloat16*)(smraw + 34816);  // ld 120
    float* Cs = (float*)smraw;                            // ld 112 (reuse)
    const int tid = threadIdx.x;
    const int w = tid >> 5;
    const int l = tid & 31;
    const int mBase = blockIdx.x * 128;

    // A: warp w owns rows 16w..16w+15; lane l loads float4 of cols 4l..4l+3
#pragma unroll
    for (int r = 0; r < 16; r++) {
        int row = w * 16 + r;
        int gn = mBase + row;
        float4 v = (gn < NN) ? *(const float4*)(X + gn * 128 + 4 * l)
                             : make_float4(0.f, 0.f, 0.f, 0.f);
        bf4 o;
        o.a = __floats2bfloat162_rn(v.x, v.y);
        o.b = __floats2bfloat162_rn(v.z, v.w);
        *(bf4*)&As[row * 136 + 4 * l] = o;
    }
    // B: warp w owns k-rows 16w..16w+15; lane covers cols l, l+32, l+64, l+96
#pragma unroll
    for (int r = 0; r < 16; r++) {
        int k = w * 16 + r;
#pragma unroll
        for (int cc = 0; cc < 4; cc++) {
            int n = l + 32 * cc;
            if (n < 112)
                Bs[k * 120 + n] = __float2bfloat16((n < 100) ? W1[k * 100 + n] : 0.f);
        }
    }
    __syncthreads();

    wmma::fragment<wmma::accumulator, 16, 16, 16, float> c[7];
#pragma unroll
    for (int n = 0; n < 7; n++) wmma::fill_fragment(c[n], 0.f);
#pragma unroll
    for (int k = 0; k < 8; k++) {
        wmma::fragment<wmma::matrix_a, 16, 16, 16, __nv_bfloat16, wmma::row_major> a;
        wmma::load_matrix_sync(a, As + (w * 16) * 136 + k * 16, 136);
#pragma unroll
        for (int n = 0; n < 7; n++) {
            wmma::fragment<wmma::matrix_b, 16, 16, 16, __nv_bfloat16, wmma::row_major> b;
            wmma::load_matrix_sync(b, Bs + (k * 16) * 120 + n * 16, 120);
            wmma::mma_sync(c[n], a, b, c[n]);
        }
    }
    __syncthreads();   // all warps done reading As/Bs before Cs overwrite
#pragma unroll
    for (int n = 0; n < 7; n++)
        wmma::store_matrix_sync(Cs + (w * 16) * 112 + n * 16, c[n], 112, wmma::mem_row_major);
    __syncthreads();

    // epilogue: lanes 0..24 each own one 4-col chunk; 16 rows per warp
    if (l < 25) {
#pragma unroll
        for (int r = 0; r < 16; r++) {
            int row = w * 16 + r;
            int gn = mBase + row;
            if (gn < NN) {
                const float* p = Cs + row * 112 + l * 4;
                bf4 o;
                o.a = __floats2bfloat162_rn(p[0], p[1]);
                o.b = __floats2bfloat162_rn(p[2], p[3]);
                d_hp1b[gn * 25 + l] = o;
            }
        }
    }
}

// ---------------- fused layer-1 gather + proj2 ----------------
// Block: 40 nodes. Phase 1 (1000 threads = 40 nodes x 25 chunks): CSR gather of
// bf16 messages, mean/bias/relu, h1 row -> smem. Phase 2 (400 threads = 40
// nodes x 10 output-pairs): hp2 = h1 @ W2 via f32x2.
__global__ void __launch_bounds__(1000) gp_kernel(const float* __restrict__ b1,
                                                  const float* __restrict__ W2) {
    __shared__ float h1s[40 * 104];
    __shared__ ull W2d[100 * 10];
    int tid = threadIdx.x;
    int n0 = blockIdx.x * 40;

    // stage W2 as f32x2 pairs: W2d[k*10+p] = (W2[k][2p], W2[k][2p+1])
    {
        float2 wv = *(const float2*)(W2 + 2 * tid);   // tid = k*10+p exactly
        W2d[tid] = pk2(wv.x, wv.y);
    }

    // phase 1: gather
    int nl = tid / 25;
    int c = tid - nl * 25;
    int n = n0 + nl;
    int row0 = d_rowstart[n];
    int row1 = d_rowstart[n + 1];
    int deg = row1 - row0;

    float4 a0 = make_float4(0.f, 0.f, 0.f, 0.f);
    float4 a1 = make_float4(0.f, 0.f, 0.f, 0.f);
    int j = row0;
    for (; j + 1 < row1; j += 2) {
        int s0 = __ldg(&d_csr[j]);
        int s1 = __ldg(&d_csr[j + 1]);
        bf4 v0 = d_hp1b[s0 * 25 + c];
        bf4 v1 = d_hp1b[s1 * 25 + c];
        float2 f0a = __bfloat1622float2(v0.a), f0b = __bfloat1622float2(v0.b);
        float2 f1a = __bfloat1622float2(v1.a), f1b = __bfloat1622float2(v1.b);
        a0.x += f0a.x; a0.y += f0a.y; a0.z += f0b.x; a0.w += f0b.y;
        a1.x += f1a.x; a1.y += f1a.y; a1.z += f1b.x; a1.w += f1b.y;
    }
    if (j < row1) {
        int s = __ldg(&d_csr[j]);
        bf4 v = d_hp1b[s * 25 + c];
        float2 fa = __bfloat1622float2(v.a), fb = __bfloat1622float2(v.b);
        a0.x += fa.x; a0.y += fa.y; a0.z += fb.x; a0.w += fb.y;
    }
    float4 v;
    if (deg > 0) {
        float inv = 1.f / (float)deg;
        v = make_float4((a0.x + a1.x) * inv, (a0.y + a1.y) * inv,
                        (a0.z + a1.z) * inv, (a0.w + a1.w) * inv);
    } else {
        bf4 sv = d_hp1b[n * 25 + c];
        float2 fa = __bfloat1622float2(sv.a), fb = __bfloat1622float2(sv.b);
        v = make_float4(fa.x, fa.y, fb.x, fb.y);
    }
    float4 b = *(const float4*)(b1 + c * 4);
    float4 r = make_float4(fmaxf(v.x + b.x, 0.f), fmaxf(v.y + b.y, 0.f),
                           fmaxf(v.z + b.z, 0.f), fmaxf(v.w + b.w, 0.f));
    *(float4*)&h1s[nl * 104 + c * 4] = r;
    __syncthreads();

    // phase 2: hp2 = h1 @ W2 (node, output-pair) per thread, 2 accumulators
    if (tid < 400) {
        int node = tid / 10;
        int p = tid - node * 10;
        const float* hrow = &h1s[node * 104];
        ull acc0 = 0, acc1 = 0;
#pragma unroll 5
        for (int k = 0; k < 100; k += 2) {
            fma2(acc0, dup2(hrow[k]),     W2d[k * 10 + p]);
            fma2(acc1, dup2(hrow[k + 1]), W2d[(k + 1) * 10 + p]);
        }
        float lo = f2lo(acc0) + f2lo(acc1);
        float hi = f2hi(acc0) + f2hi(acc1);
        int gn = n0 + node;
        *(float2*)(d_hp2 + gn * 20 + 2 * p) = make_float2(lo, hi);
    }
}

// ---------------- layer-2 gather + fused graph pooling ----------------
__global__ void __launch_bounds__(256) gather2_kernel(const float* __restrict__ b2,
                                                      const int* __restrict__ n2g) {
    int i = blockIdx.x * 256 + threadIdx.x;
    if (i >= NN * 5) return;
    int n = i / 5;
    int c = i - n * 5;
    int row0 = d_rowstart[n];
    int row1 = d_rowstart[n + 1];
    int deg = row1 - row0;

    float4 a0 = make_float4(0.f, 0.f, 0.f, 0.f);
    float4 a1 = make_float4(0.f, 0.f, 0.f, 0.f);
    int j = row0;
    for (; j + 1 < row1; j += 2) {
        int s0 = __ldg(&d_csr[j]);
        int s1 = __ldg(&d_csr[j + 1]);
        float4 f0 = *(const float4*)(d_hp2 + s0 * 20 + c * 4);
        float4 f1 = *(const float4*)(d_hp2 + s1 * 20 + c * 4);
        a0.x += f0.x; a0.y += f0.y; a0.z += f0.z; a0.w += f0.w;
        a1.x += f1.x; a1.y += f1.y; a1.z += f1.z; a1.w += f1.w;
    }
    if (j < row1) {
        int s = __ldg(&d_csr[j]);
        float4 f = *(const float4*)(d_hp2 + s * 20 + c * 4);
        a0.x += f.x; a0.y += f.y; a0.z += f.z; a0.w += f.w;
    }
    float4 v;
    if (deg > 0) {
        float inv = 1.f / (float)deg;
        v = make_float4((a0.x + a1.x) * inv, (a0.y + a1.y) * inv,
                        (a0.z + a1.z) * inv, (a0.w + a1.w) * inv);
    } else {
        v = *(const float4*)(d_hp2 + n * 20 + c * 4);
    }
    float4 b = *(const float4*)(b2 + c * 4);
    float4 r = make_float4(fmaxf(v.x + b.x, 0.f), fmaxf(v.y + b.y, 0.f),
                           fmaxf(v.z + b.z, 0.f), fmaxf(v.w + b.w, 0.f));
    int g = n2g[n];
    float* gs = d_gsum + g * 20 + c * 4;
    atomicAdd(gs + 0, r.x);
    atomicAdd(gs + 1, r.y);
    atomicAdd(gs + 2, r.z);
    atomicAdd(gs + 3, r.w);
    if (c == 0) atomicAdd(&d_gcnt[g], 1.f);
}

// ---------------- mlp1: y1 = (hg (x) sf) @ Wf1 + bf1, f32x2 over graph pairs ----------------
__global__ void __launch_bounds__(128) mlp1_kernel(const float* __restrict__ sf,
                                                   const float* __restrict__ Wf1,
                                                   const float* __restrict__ bf1) {
    __shared__ float fs[640 * 8];
    int g0 = blockIdx.x * 8;
    int tid = threadIdx.x;
    for (int idx = tid; idx < 640 * 8; idx += 128) {
        int j = idx >> 3;
        int g = idx & 7;
        int k = j >> 5, s = j & 31;
        float inv = 1.f / fmaxf(d_gcnt[g0 + g], 1.f);
        fs[idx] = d_gsum[(g0 + g) * 20 + k] * inv * sf[(g0 + g) * 32 + s];
    }
    __syncthreads();
    int o = tid;
    ull acc[4] = {0, 0, 0, 0};
#pragma unroll 4
    for (int j = 0; j < 640; j++) {
        ull wd = dup2(Wf1[j * 128 + o]);
#pragma unroll
        for (int p = 0; p < 4; p++) {
            ull a = *(const ull*)&fs[j * 8 + 2 * p];
            fma2(acc[p], a, wd);
        }
    }
    float b = bf1[o];
#pragma unroll
    for (int p = 0; p < 4; p++) {
        d_y1[(g0 + 2 * p) * 128 + o] = f2lo(acc[p]) + b;
        d_y1[(g0 + 2 * p + 1) * 128 + o] = f2hi(acc[p]) + b;
    }
}

// ---------------- BatchNorm stats ----------------
template<int C>
__global__ void bnstats_kernel() {
    const float* __restrict__ Y = (C == 128) ? (const float*)d_y1 : (const float*)d_y2;
    float* __restrict__ stat = (C == 128) ? d_stat1 : d_stat2;
    int c = blockIdx.x;
    float s = 0.f, q = 0.f;
    for (int r = threadIdx.x; r < NG; r += 256) {
        float x = Y[r * C + c];
        s += x; q += x * x;
    }
#pragma unroll
    for (int o = 16; o > 0; o >>= 1) {
        s += __shfl_down_sync(0xffffffff, s, o);
        q += __shfl_down_sync(0xffffffff, q, o);
    }
    __shared__ float ss[8], sq[8];
    int w = threadIdx.x >> 5, l = threadIdx.x & 31;
    if (l == 0) { ss[w] = s; sq[w] = q; }
    __syncthreads();
    if (threadIdx.x == 0) {
        float S = 0.f, Q = 0.f;
#pragma unroll
        for (int i = 0; i < 8; i++) { S += ss[i]; Q += sq[i]; }
        float mu = S / (float)NG;
        float var = Q / (float)NG - mu * mu;
        stat[c] = mu;
        stat[C + c] = rsqrtf(var + 1e-5f);
    }
}

// ---------------- mlp2 ----------------
__global__ void mlp2_kernel(const float* __restrict__ Wf2, const float* __restrict__ bf2,
                            const float* __restrict__ g1, const float* __restrict__ be1) {
    int i = blockIdx.x * blockDim.x + threadIdx.x;
    int g = i >> 5, o = i & 31;
    float acc = 0.f;
    for (int k = 0; k < 128; k++) {
        float x = d_y1[g * 128 + k];
        x = fmaxf((x - d_stat1[k]) * d_stat1[128 + k] * g1[k] + be1[k], 0.f);
        acc += x * Wf2[k * 32 + o];
    }
    d_y2[g * 32 + o] = acc + bf2[o];
}

// ---------------- mlp3 ----------------
__global__ void mlp3_kernel(const float* __restrict__ Wf3, const float* __restrict__ bf3,
                            const float* __restrict__ g2, const float* __restrict__ be2,
                            float* __restrict__ out) {
    int i = blockIdx.x * blockDim.x + threadIdx.x;
    int g = i >> 3, o = i & 7;
    float acc = 0.f;
#pragma unroll
    for (int k = 0; k < 32; k++) {
        float x = d_y2[g * 32 + k];
        x = fmaxf((x - d_stat2[k]) * d_stat2[32 + k] * g2[k] + be2[k], 0.f);
        acc += x * Wf3[k * 8 + o];
    }
    out[i] = acc + bf3[o];
}

// ---------------- tail cleanup: restore zero-invariant for next replay ----------------
__global__ void cleanup_kernel() {
    int i = blockIdx.x * blockDim.x + threadIdx.x;
    int st = gridDim.x * blockDim.x;
    for (int j = i; j < NN; j += st) d_deg[j] = 0;
    for (int j = i; j < NG * 20; j += st) d_gsum[j] = 0.f;
    for (int j = i; j < NG; j += st) d_gcnt[j] = 0.f;
}

extern "C" void kernel_launch(void* const* d_in, const int* in_sizes, int n_in,
                              void* d_out, int out_size) {
    const float* feat = (const float*)d_in[0];
    const float* sf   = (const float*)d_in[1];
    const int*   src  = (const int*)d_in[2];
    const int*   dst  = (const int*)d_in[3];
    const int*   n2g  = (const int*)d_in[4];
    const float* W1   = (const float*)d_in[5];
    const float* b1   = (const float*)d_in[6];
    const float* W2   = (const float*)d_in[7];
    const float* b2   = (const float*)d_in[8];
    const float* Wf1  = (const float*)d_in[9];
    const float* bf1  = (const float*)d_in[10];
    const float* g1   = (const float*)d_in[11];
    const float* be1  = (const float*)d_in[12];
    const float* Wf2  = (const float*)d_in[13];
    const float* bf2  = (const float*)d_in[14];
    const float* g2   = (const float*)d_in[15];
    const float* be2  = (const float*)d_in[16];
    const float* Wf3  = (const float*)d_in[17];
    const float* bf3  = (const float*)d_in[18];
    float* out = (float*)d_out;

    static bool attr_set = false;
    if (!attr_set) {
        cudaFuncSetAttribute(proj1_kernel,
                             cudaFuncAttributeMaxDynamicSharedMemorySize, 65536);
        attr_set = true;
    }

    deg_kernel<<<(NE + 255) / 256, 256>>>(dst);                    // 1
    sumA_kernel<<<98, 1024>>>();                                   // 2
    scanC_kernel<<<98, 1024>>>();                                  // 3
    proj1_kernel<<<782, 256, 65536>>>(feat, W1);                   // 4  (ncu slot)
    fill_kernel<<<(NE + 255) / 256, 256>>>(src, dst);              // 5
    gp_kernel<<<NN / 40, 1000>>>(b1, W2);                          // 6  gather1+proj2
    gather2_kernel<<<(NN * 5 + 255) / 256, 256>>>(b2, n2g);        // 7

    mlp1_kernel<<<NG / 8, 128>>>(sf, Wf1, bf1);                    // 8
    bnstats_kernel<128><<<128, 256>>>();                           // 9
    mlp2_kernel<<<NG * 32 / 256, 256>>>(Wf2, bf2, g1, be1);        // 10
    bnstats_kernel<32><<<32, 256>>>();                             // 11
    mlp3_kernel<<<NG * 8 / 256, 256>>>(Wf3, bf3, g2, be2, out);    // 12
    cleanup_kernel<<<256, 256>>>();                                // 13
}